// round 12
// baseline (speedup 1.0000x reference)
#include <cuda_runtime.h>
#include <cuda_fp16.h>
#include <cstdint>

// NeiAttention, fused per-tile kernel (round 12).
// K0: W -> fp16 once.  KF (grid 4x512, 256 thr, 2 CTAs/SM): per 8-node tile:
//   stage A fp16 (LDG+cvt+STS) + W fp16 (cp.async) + x fp16
//   y = x@W (MMA) ; logits = a.y, softmax (fp32) ; z = sum(alpha*a) fp16 ; out = z@W^T + b (MMA)
// No y/z DRAM round-trips; wave pipelining across 2 CTAs/SM keeps HBM busy.

__device__ __half g_w16[128 * 192];

// smem byte offsets
#define WB   0          // W fp16 [128 d][192 k], stride 400
#define AB   51200      // A fp16 [128 r][192 k], stride 400
#define XB   102400     // x fp16 [8 r][128 d], stride 272 (ldsm overreads rows 8-15: harmless)
#define ZB   104576     // z fp16 [8 n][192 k], stride 400 (ldsm overreads rows 8-15: harmless)
#define YB   107776     // y fp16 [8 n][192 k], compact 384
#define LOGB 110848     // 128 f32
#define EXB  111360     // 128 f32
#define ALB  111872     // 128 f32
#define SMEM_BYTES 112384

__device__ __forceinline__ uint32_t smem_u32(const void* p) {
    uint32_t a;
    asm("{ .reg .u64 t; cvta.to.shared.u64 t, %1; cvt.u32.u64 %0, t; }" : "=r"(a) : "l"(p));
    return a;
}
__device__ __forceinline__ uint32_t pack_f16x2(float lo, float hi) {
    uint32_t r;
    asm("cvt.rn.f16x2.f32 %0, %1, %2;" : "=r"(r) : "f"(hi), "f"(lo));
    return r;
}
__device__ __forceinline__ void ldsm4(uint32_t r[4], uint32_t addr) {
    asm volatile("ldmatrix.sync.aligned.m8n8.x4.shared.b16 {%0,%1,%2,%3}, [%4];"
                 : "=r"(r[0]), "=r"(r[1]), "=r"(r[2]), "=r"(r[3]) : "r"(addr));
}
__device__ __forceinline__ void ldsm4t(uint32_t r[4], uint32_t addr) {
    asm volatile("ldmatrix.sync.aligned.m8n8.x4.trans.shared.b16 {%0,%1,%2,%3}, [%4];"
                 : "=r"(r[0]), "=r"(r[1]), "=r"(r[2]), "=r"(r[3]) : "r"(addr));
}
__device__ __forceinline__ void mma_f16(float d[4], const uint32_t a[4],
                                        uint32_t b0, uint32_t b1) {
    asm volatile(
        "mma.sync.aligned.m16n8k16.row.col.f32.f16.f16.f32 "
        "{%0,%1,%2,%3}, {%4,%5,%6,%7}, {%8,%9}, {%0,%1,%2,%3};"
        : "+f"(d[0]), "+f"(d[1]), "+f"(d[2]), "+f"(d[3])
        : "r"(a[0]), "r"(a[1]), "r"(a[2]), "r"(a[3]), "r"(b0), "r"(b1));
}
__device__ __forceinline__ void cpa16(uint32_t dst, const void* src) {
    asm volatile("cp.async.cg.shared.global [%0], [%1], 16;" :: "r"(dst), "l"(src));
}
__device__ __forceinline__ void cp_commit() { asm volatile("cp.async.commit_group;" ::: "memory"); }
template <int N>
__device__ __forceinline__ void cp_wait() { asm volatile("cp.async.wait_group %0;" :: "n"(N) : "memory"); }
__device__ __forceinline__ float shflx(float v, int m) { return __shfl_xor_sync(0xffffffffu, v, m); }
__device__ __forceinline__ void sts_f16x4(char* dst, float4 v) {
    uint2 w;
    w.x = pack_f16x2(v.x, v.y);
    w.y = pack_f16x2(v.z, v.w);
    *(uint2*)dst = w;
}

// ============================ K0: W -> fp16 ============================
__global__ __launch_bounds__(256, 1)
void k0_wcvt(const float* __restrict__ W1_w)
{
    int i = blockIdx.x * 256 + threadIdx.x;
    float2 v = ((const float2*)W1_w)[i];
    ((uint32_t*)g_w16)[i] = pack_f16x2(v.x, v.y);
}

// ============================ KF: fused per-tile ============================
__global__ __launch_bounds__(256, 2)
void kf(const float* __restrict__ x,
        const float* __restrict__ rel,
        const float* __restrict__ nod,
        const float* __restrict__ Wb,
        float* __restrict__ out)
{
    extern __shared__ char sm[];
    const uint32_t sb = smem_u32(sm);
    const int tid = threadIdx.x;
    const int wid = tid >> 5, lid = tid & 31;
    const int g = lid >> 2, t4 = lid & 3;
    const int sel = lid >> 3, lr = lid & 7;

    const int bb = blockIdx.y, nc = blockIdx.x;
    const size_t row0  = (size_t)bb * 512 + (size_t)nc * 128;
    const int    nbase = bb * 32 + nc * 8;

    float* sLog = (float*)(sm + LOGB);
    float* sE   = (float*)(sm + EXB);
    float* sAl  = (float*)(sm + ALB);

    // ---- W fp16 via cp.async (12 chunks/thread, compact src -> padded dst) ----
    #pragma unroll
    for (int it = 0; it < 12; it++) {
        int idx = tid + it * 256;                 // 0..3071 = r*24 + c
        int r = idx / 24, c = idx - r * 24;
        cpa16(sb + WB + (uint32_t)(r * 400 + c * 16), g_w16 + r * 192 + c * 8);
    }
    cp_commit();

    // ---- A + x: LDG fp32 -> fp16 STS ----
    {
        const float4* rp = (const float4*)(rel + row0 * 64);
        #pragma unroll
        for (int it = 0; it < 8; it++) {
            int idx = tid + it * 256;             // 2048: r*16 + c  (k 0..63)
            int r = idx >> 4, c = idx & 15;
            sts_f16x4(sm + AB + r * 400 + c * 8, rp[idx]);
        }
        const float4* np = (const float4*)(nod + row0 * 128);
        #pragma unroll
        for (int it = 0; it < 16; it++) {
            int idx = tid + it * 256;             // 4096: r*32 + c  (k 64..191)
            int r = idx >> 5, c = idx & 31;
            sts_f16x4(sm + AB + r * 400 + 128 + c * 8, np[idx]);
        }
        {
            float4 v = ((const float4*)(x + (size_t)nbase * 128))[tid];  // 256 = 8r x 32c
            int r = tid >> 5, c = tid & 31;
            sts_f16x4(sm + XB + r * 272 + c * 8, v);
        }
    }
    cp_wait<0>();
    __syncthreads();

    // ---- phase 1: y = x @ W  (12 col-tiles of 16; warp w does tile w, and w+8 if w<4) ----
    {
        const uint32_t aX = sb + XB + (uint32_t)((sel & 1) * 8 + lr) * 272u
                            + (uint32_t)(sel >> 1) * 16u;
        const int drow = (lid & 7) + ((lid >> 3) & 1) * 8;
        const int kgrp = lid >> 4;
        #pragma unroll
        for (int rep = 0; rep < 2; rep++) {
            int j = wid + rep * 8;
            if (rep == 1 && wid >= 4) break;
            const uint32_t bWy = sb + WB + (uint32_t)drow * 400u
                                 + (uint32_t)(j * 16 + kgrp * 8) * 2u;
            float y0[4] = {0.f, 0.f, 0.f, 0.f};
            float y1[4] = {0.f, 0.f, 0.f, 0.f};
            #pragma unroll
            for (int ks = 0; ks < 8; ks++) {      // K = 128 over d
                uint32_t a[4], bt[4];
                ldsm4(a, aX + ks * 32);
                ldsm4t(bt, bWy + ks * 6400);
                mma_f16(y0, a, bt[0], bt[1]);
                mma_f16(y1, a, bt[2], bt[3]);
            }
            // store row g (valid rows 0..7), fp16
            char* yp = sm + YB + g * 384 + (j * 16 + 2 * t4) * 2;
            *(uint32_t*)yp        = pack_f16x2(y0[0], y0[1]);
            *(uint32_t*)(yp + 16) = pack_f16x2(y1[0], y1[1]);
        }
    }
    __syncthreads();

    // ---- phase 2: logits = a . y  (2 threads per row) ----
    {
        int row = tid >> 1, h = tid & 1;
        const half2* ap = (const half2*)(sm + AB + row * 400 + h * 192);
        const half2* yp = (const half2*)(sm + YB + (row >> 4) * 384 + h * 192);
        float s = 0.f;
        #pragma unroll
        for (int kk = 0; kk < 48; kk++) {
            float2 a2 = __half22float2(ap[kk]);
            float2 yv = __half22float2(yp[kk]);
            s += a2.x * yv.x + a2.y * yv.y;
        }
        s += shflx(s, 1);
        if (h == 0) sLog[row] = s * 0.08838834764831845f;   // 1/sqrt(128)
    }
    __syncthreads();

    // ---- phase 3: softmax over S=16 per node ----
    float e = 0.f;
    if (tid < 128) {
        int base = tid & ~15;
        float m = -1e30f;
        #pragma unroll
        for (int q = 0; q < 16; q++) m = fmaxf(m, sLog[base + q]);
        e = __expf(sLog[tid] - m);
        sE[tid] = e;
    }
    __syncthreads();
    if (tid < 128) {
        int base = tid & ~15;
        float den = 0.f;
        #pragma unroll
        for (int q = 0; q < 16; q++) den += sE[base + q];
        sAl[tid] = e / den;
    }
    __syncthreads();

    // ---- phase 4: z[n][k-pair] = sum_s alpha * a  -> fp16 ----
    #pragma unroll
    for (int p2 = 0; p2 < 3; p2++) {
        int u = tid + 256 * p2;                   // 0..767 = n*96 + kp
        int n = u / 96, kp = u - n * 96;
        const half2* ap = (const half2*)(sm + AB) + (16 * n) * 100 + kp;
        const float* al = sAl + 16 * n;
        float z0 = 0.f, z1 = 0.f;
        #pragma unroll
        for (int s = 0; s < 16; s++) {
            float2 av = __half22float2(ap[s * 100]);
            float  a  = al[s];
            z0 += a * av.x;
            z1 += a * av.y;
        }
        *(uint32_t*)(sm + ZB + n * 400 + kp * 4) = pack_f16x2(z0, z1);
    }
    __syncthreads();

    // ---- phase 5: out = z @ W^T + b  (8 warps x 2 col-groups of 8) ----
    {
        const uint32_t aZ = sb + ZB + (uint32_t)((sel & 1) * 8 + lr) * 400u
                            + (uint32_t)(sel >> 1) * 16u;
        const uint32_t bW0 = sb + WB + (uint32_t)(wid * 8 + lr) * 400u + (uint32_t)sel * 16u;
        const uint32_t bW1 = bW0 + 64u * 400u;    // cols 64 + wid*8
        float o0[4] = {0.f, 0.f, 0.f, 0.f};
        float o1[4] = {0.f, 0.f, 0.f, 0.f};
        #pragma unroll
        for (int k2 = 0; k2 < 6; k2++) {          // K = 192, 2 ksteps per iter
            uint32_t b0[4], b1[4], a0[4], a1[4];
            ldsm4(a0, aZ + (2 * k2) * 32);
            ldsm4(a1, aZ + (2 * k2 + 1) * 32);
            ldsm4(b0, bW0 + k2 * 64);
            ldsm4(b1, bW1 + k2 * 64);
            mma_f16(o0, a0, b0[0], b0[1]);
            mma_f16(o0, a1, b0[2], b0[3]);
            mma_f16(o1, a0, b1[0], b1[1]);
            mma_f16(o1, a1, b1[2], b1[3]);
        }
        // rows g (0..7) valid
        float* op = out + (size_t)(nbase + g) * 128;
        int c0 = wid * 8 + 2 * t4;
        float2 w0, w1;
        w0.x = o0[0] + __ldg(Wb + c0);
        w0.y = o0[1] + __ldg(Wb + c0 + 1);
        w1.x = o1[0] + __ldg(Wb + c0 + 64);
        w1.y = o1[1] + __ldg(Wb + c0 + 65);
        *(float2*)(op + c0)      = w0;
        *(float2*)(op + c0 + 64) = w1;
    }
}

extern "C" void kernel_launch(void* const* d_in, const int* in_sizes, int n_in,
                              void* d_out, int out_size)
{
    const float* x          = (const float*)d_in[0];
    const float* x_nei_rel  = (const float*)d_in[1];
    const float* x_nei_node = (const float*)d_in[2];
    const float* W1_w       = (const float*)d_in[3];
    const float* W1_b       = (const float*)d_in[4];
    float* out = (float*)d_out;

    cudaFuncSetAttribute(kf, cudaFuncAttributeMaxDynamicSharedMemorySize, SMEM_BYTES);

    k0_wcvt<<<48, 256>>>(W1_w);
    kf<<<dim3(4, 512), 256, SMEM_BYTES>>>(x, x_nei_rel, x_nei_node, W1_b, out);
}

// round 13
// speedup vs baseline: 1.2993x; 1.2993x over previous
#include <cuda_runtime.h>
#include <cuda_fp16.h>
#include <cstdint>

// NeiAttention, 3-kernel form (round 13 = round 8 + 64-row K2 tiles @4 CTAs/SM + fp16 y).
// K1: y = x @ W            fp16 MMA (W staged fp32->fp16 in-kernel), y out fp16
// K2: logits/softmax/z     streams A once (fp32 cp.async), y fp16 in, z fp16 out, 4 CTAs/SM
// K3: out = z @ W^T + b    fp16 MMA (R8 form: z cp.async overlapped with W cvt staging)

__device__ __half g_y16[16384 * 192];
__device__ __half g_z16[16384 * 192];

__device__ __forceinline__ uint32_t smem_u32(const void* p) {
    uint32_t a;
    asm("{ .reg .u64 t; cvta.to.shared.u64 t, %1; cvt.u32.u64 %0, t; }" : "=r"(a) : "l"(p));
    return a;
}
__device__ __forceinline__ uint32_t pack_f16x2(float lo, float hi) {
    uint32_t r;
    asm("cvt.rn.f16x2.f32 %0, %1, %2;" : "=r"(r) : "f"(hi), "f"(lo));
    return r;
}
__device__ __forceinline__ void ldsm4(uint32_t r[4], uint32_t addr) {
    asm volatile("ldmatrix.sync.aligned.m8n8.x4.shared.b16 {%0,%1,%2,%3}, [%4];"
                 : "=r"(r[0]), "=r"(r[1]), "=r"(r[2]), "=r"(r[3]) : "r"(addr));
}
__device__ __forceinline__ void ldsm4t(uint32_t r[4], uint32_t addr) {
    asm volatile("ldmatrix.sync.aligned.m8n8.x4.trans.shared.b16 {%0,%1,%2,%3}, [%4];"
                 : "=r"(r[0]), "=r"(r[1]), "=r"(r[2]), "=r"(r[3]) : "r"(addr));
}
__device__ __forceinline__ void mma_f16(float d[4], const uint32_t a[4],
                                        uint32_t b0, uint32_t b1) {
    asm volatile(
        "mma.sync.aligned.m16n8k16.row.col.f32.f16.f16.f32 "
        "{%0,%1,%2,%3}, {%4,%5,%6,%7}, {%8,%9}, {%0,%1,%2,%3};"
        : "+f"(d[0]), "+f"(d[1]), "+f"(d[2]), "+f"(d[3])
        : "r"(a[0]), "r"(a[1]), "r"(a[2]), "r"(a[3]), "r"(b0), "r"(b1));
}
__device__ __forceinline__ void cpa16(uint32_t dst, const void* src) {
    asm volatile("cp.async.cg.shared.global [%0], [%1], 16;" :: "r"(dst), "l"(src));
}
__device__ __forceinline__ void cp_commit() { asm volatile("cp.async.commit_group;" ::: "memory"); }
template <int N>
__device__ __forceinline__ void cp_wait() { asm volatile("cp.async.wait_group %0;" :: "n"(N) : "memory"); }
__device__ __forceinline__ float shflx(float v, int m) { return __shfl_xor_sync(0xffffffffu, v, m); }

// ============================ K1: y = x @ W ============================
// 256 CTAs x 64 rows, 256 thr (warp grid 2x4, warp tile 32x48). R8 form; y out fp16.
#define K1_XH   0         // 64*68  = 4352 w
#define K1_WH   4352      // 128*100 = 12800 w
#define K1_WORDS 17152
#define K1_BYTES (K1_WORDS * 4)   // 68,608 B

__global__ __launch_bounds__(256, 2)
void k1_y(const float* __restrict__ x, const float* __restrict__ W1_w)
{
    extern __shared__ float sm[];
    const uint32_t sb = smem_u32(sm);
    const int tid = threadIdx.x;
    const int wid = tid >> 5, lid = tid & 31;
    const int g = lid >> 2, t4 = lid & 3;
    const int sel = lid >> 3, lr = lid & 7;
    const int wm = wid >> 2, wn = wid & 3;

    // stage x tile (64 rows, fp16, stride 68 words)
    {
        const float4* xp = (const float4*)(x + (size_t)blockIdx.x * 64 * 128);
        #pragma unroll
        for (int it = 0; it < 8; it++) {
            int idx = tid + it * 256;            // r*32 + c
            int r = idx >> 5, c = idx & 31;
            float4 v = xp[idx];
            uint2 w;
            w.x = pack_f16x2(v.x, v.y);
            w.y = pack_f16x2(v.z, v.w);
            *(uint2*)((uint32_t*)sm + K1_XH + r * 68 + 2 * c) = w;
        }
    }
    // stage W natural [d][k'] fp16 (stride 100 words)
    {
        const float4* Wv = (const float4*)W1_w;  // [128 d][192 k']
        #pragma unroll
        for (int it = 0; it < 24; it++) {
            int idx = tid + it * 256;
            int d = idx / 48, c = idx - d * 48;
            float4 v = Wv[idx];
            uint2 w;
            w.x = pack_f16x2(v.x, v.y);
            w.y = pack_f16x2(v.z, v.w);
            *(uint2*)((uint32_t*)sm + K1_WH + d * 100 + 2 * c) = w;
        }
    }
    __syncthreads();

    uint32_t aA[2];
    #pragma unroll
    for (int i = 0; i < 2; i++)
        aA[i] = sb + K1_XH * 4 + (uint32_t)(wm * 32 + i * 16 + (sel & 1) * 8 + lr) * 272u
                + (uint32_t)(sel >> 1) * 16u;
    const int drow = (lid & 7) + ((lid >> 3) & 1) * 8;
    const int kgrp = lid >> 4;
    uint32_t bT[3];
    #pragma unroll
    for (int jp = 0; jp < 3; jp++)
        bT[jp] = sb + K1_WH * 4 + (uint32_t)drow * 400u
                 + (uint32_t)(wn * 48 + jp * 16 + kgrp * 8) * 2u;

    float acc[2][6][4];
    #pragma unroll
    for (int i = 0; i < 2; i++)
        #pragma unroll
        for (int j = 0; j < 6; j++)
            #pragma unroll
            for (int q = 0; q < 4; q++) acc[i][j][q] = 0.f;

    #pragma unroll
    for (int ks = 0; ks < 8; ks++) {             // K = 128 (d)
        uint32_t a0[4], a1[4];
        ldsm4(a0, aA[0] + ks * 32);
        ldsm4(a1, aA[1] + ks * 32);
        #pragma unroll
        for (int jp = 0; jp < 3; jp++) {
            uint32_t bt[4];
            ldsm4t(bt, bT[jp] + ks * 6400);      // +16 d-rows * 400 B
            mma_f16(acc[0][2 * jp],     a0, bt[0], bt[1]);
            mma_f16(acc[0][2 * jp + 1], a0, bt[2], bt[3]);
            mma_f16(acc[1][2 * jp],     a1, bt[0], bt[1]);
            mma_f16(acc[1][2 * jp + 1], a1, bt[2], bt[3]);
        }
    }

    // write y as fp16
    #pragma unroll
    for (int i = 0; i < 2; i++) {
        int row = blockIdx.x * 64 + wm * 32 + i * 16 + g;
        #pragma unroll
        for (int j = 0; j < 6; j++) {
            int col = wn * 48 + j * 8 + 2 * t4;
            *(uint32_t*)(g_y16 + (size_t)row * 192 + col) =
                pack_f16x2(acc[i][j][0], acc[i][j][1]);
            *(uint32_t*)(g_y16 + (size_t)(row + 8) * 192 + col) =
                pack_f16x2(acc[i][j][2], acc[i][j][3]);
        }
    }
}

// ============== K2: logits, softmax, z — 64-row tiles, 4 CTAs/SM ==============
#define K2_AST  196       // A row stride (fp32 words)
#define K2_SA   0         // 64*196 = 12544 w
#define K2_SY   12544     // 384 w = 768 halves (4 nodes x 192)
#define K2_LOG  12928     // 64 f32
#define K2_EX   12992     // 64
#define K2_AL   13056     // 64
#define K2_WORDS 13120
#define K2_BYTES (K2_WORDS * 4)   // 52,480 B -> 4 CTAs/SM

__global__ __launch_bounds__(256, 4)
void k2_attn(const float* __restrict__ x_nei_rel,
             const float* __restrict__ x_nei_node)
{
    extern __shared__ float sm[];
    const uint32_t sb = smem_u32(sm);
    float*  sA  = sm + K2_SA;
    __half* sYh = (__half*)(sm + K2_SY);
    float*  sLog= sm + K2_LOG;
    float*  sE  = sm + K2_EX;
    float*  sAl = sm + K2_AL;
    const uint32_t aU = sb + K2_SA * 4, yU = sb + K2_SY * 4;

    const int tid = threadIdx.x;
    const int b = blockIdx.y, nc = blockIdx.x;          // nc 0..7 (4-node chunk)
    const size_t row0  = (size_t)b * 512 + (size_t)nc * 64;
    const int    nbase = b * 32 + nc * 4;

    // group 0: rel (k 0..63) + node k 64..95 + y (fp16)
    {
        const float4* rp = (const float4*)(x_nei_rel + row0 * 64);
        #pragma unroll
        for (int it = 0; it < 4; it++) {
            int idx = tid + it * 256;                   // 1024: r*16 + c
            int r = idx >> 4, c = idx & 15;
            cpa16(aU + (uint32_t)(r * K2_AST + c * 4) * 4u, rp + r * 16 + c);
        }
        const float4* np = (const float4*)(x_nei_node + row0 * 128);
        #pragma unroll
        for (int it = 0; it < 2; it++) {
            int idx = tid + it * 256;                   // 512: r*8 + c
            int r = idx >> 3, c = idx & 7;
            cpa16(aU + (uint32_t)(r * K2_AST + 64 + c * 4) * 4u, np + r * 32 + c);
        }
        if (tid < 96)
            cpa16(yU + (uint32_t)tid * 16u, g_y16 + (size_t)nbase * 192 + tid * 8);
        cp_commit();
        // group 1: node k 96..191
        #pragma unroll
        for (int it = 0; it < 6; it++) {
            int idx = tid + it * 256;                   // 1536: r*24 + c
            int r = idx / 24, c = idx - r * 24;
            cpa16(aU + (uint32_t)(r * K2_AST + 96 + c * 4) * 4u, np + r * 32 + 8 + c);
        }
        cp_commit();
    }

    // dots: 4 threads per row, 24 k each per phase
    const int r = tid >> 2, h = tid & 3;
    float s = 0.f;
    cp_wait<1>();
    __syncthreads();
    {
        const float*  ar = sA + r * K2_AST + h * 24;
        const __half* yr = sYh + (r >> 4) * 192 + h * 24;
        #pragma unroll
        for (int kk = 0; kk < 12; kk++) {
            float2 a2 = *(const float2*)(ar + 2 * kk);
            float2 yf = __half22float2(*(const __half2*)(yr + 2 * kk));
            s += a2.x * yf.x + a2.y * yf.y;
        }
    }
    cp_wait<0>();
    __syncthreads();
    {
        const float*  ar = sA + r * K2_AST + 96 + h * 24;
        const __half* yr = sYh + (r >> 4) * 192 + 96 + h * 24;
        #pragma unroll
        for (int kk = 0; kk < 12; kk++) {
            float2 a2 = *(const float2*)(ar + 2 * kk);
            float2 yf = __half22float2(*(const __half2*)(yr + 2 * kk));
            s += a2.x * yf.x + a2.y * yf.y;
        }
    }
    s += shflx(s, 1);
    s += shflx(s, 2);
    if (h == 0) sLog[r] = s * 0.08838834764831845f;     // 1/sqrt(128)
    __syncthreads();

    // softmax over S=16 per node (64 rows = 4 nodes)
    float e = 0.f;
    if (tid < 64) {
        int base = tid & ~15;
        float m = -1e30f;
        #pragma unroll
        for (int q = 0; q < 16; q++) m = fmaxf(m, sLog[base + q]);
        e = __expf(sLog[tid] - m);
        sE[tid] = e;
    }
    __syncthreads();
    if (tid < 64) {
        int base = tid & ~15;
        float den = 0.f;
        #pragma unroll
        for (int q = 0; q < 16; q++) den += sE[base + q];
        sAl[tid] = e / den;
    }
    __syncthreads();

    // z[n][k-pair] = sum_s alpha * a  -> fp16   (4 nodes x 96 pairs = 384)
    #pragma unroll
    for (int p = 0; p < 2; p++) {
        int u = tid + 256 * p;
        if (u < 384) {
            int n = u / 96, dp = u - n * 96;
            const float* ap = sA + (n * 16) * K2_AST + 2 * dp;
            const float* al = sAl + n * 16;
            float z0 = 0.f, z1 = 0.f;
            #pragma unroll
            for (int q = 0; q < 16; q++) {
                float2 av = *(const float2*)(ap + q * K2_AST);
                float  a  = al[q];
                z0 += a * av.x;
                z1 += a * av.y;
            }
            *(uint32_t*)(g_z16 + (size_t)(nbase + n) * 192 + 2 * dp) = pack_f16x2(z0, z1);
        }
    }
}

// ============================ K3: out = z @ W^T + b ============================
// 256 CTAs x 64 rows, 256 thr. R8 form: z via cp.async, W fp32 cvt staged in overlap.
#define K3_ZH   0         // 64*100 = 6400 w
#define K3_WH   6400      // 128*100 = 12800 w
#define K3_WORDS 19200
#define K3_BYTES (K3_WORDS * 4)   // 76,800 B

__global__ __launch_bounds__(256, 2)
void k3_out(const float* __restrict__ W1_w,
            const float* __restrict__ W1_b,
            float* __restrict__ out)
{
    extern __shared__ float sm[];
    const uint32_t sb = smem_u32(sm);
    const int tid = threadIdx.x;
    const int wid = tid >> 5, lid = tid & 31;
    const int g = lid >> 2, t4 = lid & 3;
    const int sel = lid >> 3, lr = lid & 7;
    const int wm = wid >> 2, wn = wid & 3;

    // stage z rows (fp16) via cp.async
    {
        const __half* zp = g_z16 + (size_t)blockIdx.x * 64 * 192;
        #pragma unroll
        for (int it = 0; it < 6; it++) {
            int idx = tid + it * 256;            // r*24 + c
            int r = idx / 24, c = idx - r * 24;
            cpa16(sb + K3_ZH * 4 + (uint32_t)(r * 100 + c * 4) * 4u, zp + r * 192 + c * 8);
        }
        cp_commit();
    }
    // stage W natural [d][k] fp16 synchronously (overlaps the z flight)
    {
        const float4* Wv = (const float4*)W1_w;
        #pragma unroll
        for (int it = 0; it < 24; it++) {
            int idx = tid + it * 256;
            int d = idx / 48, c = idx - d * 48;
            float4 v = Wv[idx];
            uint2 w;
            w.x = pack_f16x2(v.x, v.y);
            w.y = pack_f16x2(v.z, v.w);
            *(uint2*)((uint32_t*)sm + K3_WH + d * 100 + 2 * c) = w;
        }
    }
    cp_wait<0>();
    __syncthreads();

    uint32_t aA[2], bA[2];
    #pragma unroll
    for (int i = 0; i < 2; i++)
        aA[i] = sb + K3_ZH * 4 + (uint32_t)(wm * 32 + i * 16 + (sel & 1) * 8 + lr) * 400u
                + (uint32_t)(sel >> 1) * 16u;
    #pragma unroll
    for (int jp = 0; jp < 2; jp++)
        bA[jp] = sb + K3_WH * 4 + (uint32_t)(wn * 32 + jp * 16 + (sel >> 1) * 8 + lr) * 400u
                 + (uint32_t)(sel & 1) * 16u;

    float acc[2][4][4];
    #pragma unroll
    for (int i = 0; i < 2; i++)
        #pragma unroll
        for (int j = 0; j < 4; j++)
            #pragma unroll
            for (int q = 0; q < 4; q++) acc[i][j][q] = 0.f;

    #pragma unroll
    for (int ks = 0; ks < 12; ks++) {            // K = 192
        uint32_t a0[4], a1[4], b0[4], b1[4];
        ldsm4(a0, aA[0] + ks * 32);
        ldsm4(a1, aA[1] + ks * 32);
        ldsm4(b0, bA[0] + ks * 32);
        ldsm4(b1, bA[1] + ks * 32);
        mma_f16(acc[0][0], a0, b0[0], b0[1]);
        mma_f16(acc[0][1], a0, b0[2], b0[3]);
        mma_f16(acc[0][2], a0, b1[0], b1[1]);
        mma_f16(acc[0][3], a0, b1[2], b1[3]);
        mma_f16(acc[1][0], a1, b0[0], b0[1]);
        mma_f16(acc[1][1], a1, b0[2], b0[3]);
        mma_f16(acc[1][2], a1, b1[0], b1[1]);
        mma_f16(acc[1][3], a1, b1[2], b1[3]);
    }

    #pragma unroll
    for (int i = 0; i < 2; i++) {
        int row = blockIdx.x * 64 + wm * 32 + i * 16 + g;
        #pragma unroll
        for (int j = 0; j < 4; j++) {
            int col = wn * 32 + j * 8 + 2 * t4;
            float b0 = __ldg(W1_b + col), b1 = __ldg(W1_b + col + 1);
            float2 w0 = { acc[i][j][0] + b0, acc[i][j][1] + b1 };
            float2 w1 = { acc[i][j][2] + b0, acc[i][j][3] + b1 };
            *(float2*)(out + (size_t)row * 128 + col)       = w0;
            *(float2*)(out + (size_t)(row + 8) * 128 + col) = w1;
        }
    }
}

extern "C" void kernel_launch(void* const* d_in, const int* in_sizes, int n_in,
                              void* d_out, int out_size)
{
    const float* x          = (const float*)d_in[0];
    const float* x_nei_rel  = (const float*)d_in[1];
    const float* x_nei_node = (const float*)d_in[2];
    const float* W1_w       = (const float*)d_in[3];
    const float* W1_b       = (const float*)d_in[4];
    float* out = (float*)d_out;

    cudaFuncSetAttribute(k1_y,    cudaFuncAttributeMaxDynamicSharedMemorySize, K1_BYTES);
    cudaFuncSetAttribute(k2_attn, cudaFuncAttributeMaxDynamicSharedMemorySize, K2_BYTES);
    cudaFuncSetAttribute(k3_out,  cudaFuncAttributeMaxDynamicSharedMemorySize, K3_BYTES);

    k1_y<<<256, 256, K1_BYTES>>>(x, W1_w);
    k2_attn<<<dim3(8, 512), 256, K2_BYTES>>>(x_nei_rel, x_nei_node);
    k3_out<<<256, 256, K3_BYTES>>>(W1_w, W1_b, out);
}